// round 16
// baseline (speedup 1.0000x reference)
#include <cuda_runtime.h>
#include <cuda_fp16.h>
#include <cstdint>

#define NN 50000
#define EE 800000
#define GG 512
#define EFD 16

// ---------------- scratch (no allocations allowed) ----------------
__device__ float g_bufA[NN * 256];
__device__ float g_bufB[NN * 256];
__device__ float g_agg[NN * 256];
__device__ __half g_uh[NN * 256];
__device__ __half g_sh[NN * 256];
__device__ float g_deg[NN];
__device__ float g_gcnt[GG];

// ---------------- helpers ----------------
__device__ __forceinline__ uint32_t f2tf32(float x) {
    uint32_t r;
    asm("cvt.rna.tf32.f32 %0, %1;" : "=r"(r) : "f"(x));
    return r;
}
__device__ __forceinline__ uint32_t smem_u32(const void* p) {
    uint32_t a;
    asm("{ .reg .u64 t; cvta.to.shared.u64 t, %1; cvt.u32.u64 %0, t; }" : "=r"(a) : "l"(p));
    return a;
}
__device__ __forceinline__ void cp16(uint32_t saddr, const void* gaddr) {
    asm volatile("cp.async.ca.shared.global [%0], [%1], 16;" :: "r"(saddr), "l"(gaddr) : "memory");
}
#define CP_COMMIT() asm volatile("cp.async.commit_group;" ::: "memory")
#define CP_WAIT(n)  asm volatile("cp.async.wait_group %0;" :: "n"(n) : "memory")

// D += A(16x8,row) * B(8x8,col), tf32 inputs, f32 accum
__device__ __forceinline__ void mma_tf32(float* d, const uint32_t* a, const uint32_t* b) {
    asm volatile(
        "mma.sync.aligned.m16n8k8.row.col.f32.tf32.tf32.f32 "
        "{%0,%1,%2,%3}, {%4,%5,%6,%7}, {%8,%9}, {%0,%1,%2,%3};"
        : "+f"(d[0]), "+f"(d[1]), "+f"(d[2]), "+f"(d[3])
        : "r"(a[0]), "r"(a[1]), "r"(a[2]), "r"(a[3]), "r"(b[0]), "r"(b[1]));
}

__global__ void count_kernel(const int* __restrict__ dst, const int* __restrict__ gid,
                             float* __restrict__ deg, float* __restrict__ gcnt) {
    int i = blockIdx.x * blockDim.x + threadIdx.x;
    if (i < EE) atomicAdd(&deg[dst[i]], 1.0f);
    if (i < NN) atomicAdd(&gcnt[gid[i]], 1.0f);
}

// ---------------- fused dense kernel ----------------
// u[:,co:+FK] = x@Wmx[:,co:+FK] + bm;  s[:,co:+FK] = x@Ws[:,co:+FK] + bs  (fp16 out)
template <int FIN, int F, int FK, int TILE>
__global__ __launch_bounds__(256)
void us_kernel(const float* __restrict__ xin,
               const float* __restrict__ Wmx, const float* __restrict__ Ws,
               const float* __restrict__ bm, const float* __restrict__ bs,
               __half2* __restrict__ uout, __half2* __restrict__ sout, int col_off)
{
    constexpr int KP = FIN + 4;
    constexpr int KC8 = FIN / 8;
    constexpr int N2 = 2 * FK;
    constexpr int NT = FK / 8;
    constexpr int MI = TILE / 64;
    constexpr int TPR = 256 / TILE;
    constexpr int W_U32 = FIN * N2;

    extern __shared__ char smem[];
    uint32_t* Wp = (uint32_t*)smem;
    float* Abuf = (float*)(smem + (size_t)W_U32 * 4);

    const int tid = threadIdx.x;
    const int w = tid >> 5, lane = tid & 31;
    const int wm = w >> 1, wn = w & 1;
    const int g = lane >> 2, tg = lane & 3;
    const int row = tid / TPR, h = tid % TPR;
    const uint32_t sbA = smem_u32(Abuf);

    for (int i = tid; i < FIN * N2; i += 256) {
        int k = i / N2, n = i % N2;
        float wv = (n < FK) ? Wmx[k * F + col_off + n] : Ws[k * F + col_off + (n - FK)];
        uint32_t val = f2tf32(wv);
        int T = n >> 3, kc = k >> 3;
        Wp[((T * KC8 + kc) * 32 + (n & 7) * 4 + (k & 3)) * 2 + ((k >> 2) & 1)] = val;
    }

    const int nTiles = (NN + TILE - 1) / TILE;
    const int stride = gridDim.x;

    auto gather = [&](int tile) {
        int grow = tile * TILE + row;
        if (grow >= NN) grow = NN - 1;
        uint32_t arow = sbA + (uint32_t)(row * KP) * 4;
        const char* xr = (const char*)(xin + (size_t)grow * FIN);
        #pragma unroll
        for (int c = h; c < FIN / 4; c += TPR) cp16(arow + c * 16, xr + c * 16);
    };

    int t0 = blockIdx.x;
    gather(t0);
    CP_COMMIT();

    __half2* outp = wn ? sout : uout;
    const float* bias = wn ? bs : bm;

    for (int tile = t0; tile < nTiles; tile += stride) {
        CP_WAIT(0);
        __syncthreads();

        float acc[MI][NT][4];
        #pragma unroll
        for (int mi = 0; mi < MI; mi++)
            #pragma unroll
            for (int t = 0; t < NT; t++)
                #pragma unroll
                for (int j = 0; j < 4; j++) acc[mi][t][j] = 0.0f;

        for (int kc = 0; kc < KC8; kc++) {
            uint2 b[NT];
            #pragma unroll
            for (int t = 0; t < NT; t++)
                b[t] = *(const uint2*)&Wp[(((wn * NT + t) * KC8 + kc) * 32 + lane) * 2];
            #pragma unroll
            for (int mi = 0; mi < MI; mi++) {
                const float* ar = Abuf + (wm * (TILE / 4) + mi * 16 + g) * KP + kc * 8 + tg;
                uint32_t a[4];
                a[0] = f2tf32(ar[0]);
                a[1] = f2tf32(ar[8 * KP]);
                a[2] = f2tf32(ar[4]);
                a[3] = f2tf32(ar[8 * KP + 4]);
                #pragma unroll
                for (int t = 0; t < NT; t++)
                    mma_tf32(acc[mi][t], a, (const uint32_t*)&b[t]);
            }
        }
        __syncthreads();

        int nxt = tile + stride;
        if (nxt < nTiles) { gather(nxt); CP_COMMIT(); }

        const int base = tile * TILE;
        #pragma unroll
        for (int mi = 0; mi < MI; mi++) {
            int r0 = wm * (TILE / 4) + mi * 16 + g;
            int gr0 = base + r0, gr1 = gr0 + 8;
            #pragma unroll
            for (int t = 0; t < NT; t++) {
                int n = t * 8 + tg * 2;
                float b0 = __ldg(&bias[col_off + n]);
                float b1 = __ldg(&bias[col_off + n + 1]);
                if (gr0 < NN)
                    outp[(size_t)gr0 * (F / 2) + (col_off + n) / 2] =
                        __floats2half2_rn(acc[mi][t][0] + b0, acc[mi][t][1] + b1);
                if (gr1 < NN)
                    outp[(size_t)gr1 * (F / 2) + (col_off + n) / 2] =
                        __floats2half2_rn(acc[mi][t][2] + b0, acc[mi][t][3] + b1);
            }
        }
    }
}

// ---------------- edge kernel: agg[dst] += relu(u[src] + e @ Wme), bias pre-folded into u ----------------
// Double-buffered A/U with 2-deep cp.async group pipeline: gather(t+2) issued when buf[par]
// is released, so each tile's gather has a full iteration of lead time.
template <int F, int TILE>
__global__ __launch_bounds__(256, 2)
void edge_mma_kernel(const __half2* __restrict__ u, const float* __restrict__ efeat,
                     const int* __restrict__ src, const int* __restrict__ dst,
                     const float* __restrict__ Wme,
                     float* __restrict__ agg)
{
    constexpr int K = EFD;
    constexpr int KP = K + 4;
    constexpr int KC8 = 2;
    constexpr int NT = F / 32;
    constexpr int MI = TILE / 32;
    constexpr int TPR = 256 / TILE;
    constexpr int UW = F / 2 + 4;
    constexpr int W_U32 = K * F;
    constexpr int A_F32 = TILE * KP;
    constexpr int U_W32 = TILE * UW;

    extern __shared__ char smem[];
    uint32_t* Wp = (uint32_t*)smem;
    float* Abuf = (float*)(smem + (size_t)W_U32 * 4);                 // 2 * A_F32
    uint32_t* Ubuf = (uint32_t*)(Abuf + 2 * A_F32);                   // 2 * U_W32
    int* sdst = (int*)(Ubuf + 2 * U_W32);                             // 2 * TILE

    const int tid = threadIdx.x;
    const int w = tid >> 5, lane = tid & 31;
    const int wm = w >> 2, wn = w & 3;
    const int g = lane >> 2, tg = lane & 3;
    const int row = tid / TPR, h = tid % TPR;
    const uint32_t sbA = smem_u32(Abuf);
    const uint32_t sbU = smem_u32(Ubuf);

    for (int i = tid; i < K * F; i += 256) {
        int k = i / F, n = i % F;
        uint32_t val = f2tf32(Wme[k * F + n]);
        int T = n >> 3, kc = k >> 3;
        Wp[((T * KC8 + kc) * 32 + (n & 7) * 4 + (k & 3)) * 2 + ((k >> 2) & 1)] = val;
    }

    const int nTiles = EE / TILE;
    const int stride = gridDim.x;

    auto gather = [&](int tile, int par, int srow, int sd) {
        int base = tile * TILE;
        if (h == 0) sdst[par * TILE + row] = sd;
        uint32_t arow = sbA + (uint32_t)(par * A_F32 + row * KP) * 4;
        const char* er = (const char*)(efeat + (size_t)(base + row) * EFD);
        #pragma unroll
        for (int c = h; c < EFD / 4; c += TPR) cp16(arow + c * 16, er + c * 16);
        uint32_t urow = sbU + (uint32_t)(par * U_W32 + row * UW) * 4;
        const char* ur = (const char*)(u + (size_t)srow * (F / 2));
        #pragma unroll
        for (int c = h; c < F / 8; c += TPR) cp16(urow + c * 16, ur + c * 16);
    };

    // preamble: gathers for t0 (buf0) and t0+stride (buf1); indices for t0+2*stride in regs
    int t0 = blockIdx.x;
    int ps = src[t0 * TILE + row];
    int pd = dst[t0 * TILE + row];
    gather(t0, 0, ps, pd);
    CP_COMMIT();
    int t1 = t0 + stride;
    if (t1 < nTiles) {
        ps = src[t1 * TILE + row];
        pd = dst[t1 * TILE + row];
        gather(t1, 1, ps, pd);
        CP_COMMIT();
        int tn = t0 + 2 * stride;
        if (tn < nTiles) { ps = src[tn * TILE + row]; pd = dst[tn * TILE + row]; }
    }

    int par = 0;
    for (int tile = t0; tile < nTiles; tile += stride) {
        // FIFO completion: leaving g(t+1) outstanding guarantees g(t) done
        if (tile + stride < nTiles) CP_WAIT(1); else CP_WAIT(0);
        __syncthreads();

        float acc[MI][NT][4];
        #pragma unroll
        for (int mi = 0; mi < MI; mi++)
            #pragma unroll
            for (int t = 0; t < NT; t++)
                #pragma unroll
                for (int j = 0; j < 4; j++) acc[mi][t][j] = 0.0f;

        const float* A0 = Abuf + par * A_F32;
        #pragma unroll
        for (int kc = 0; kc < KC8; kc++) {
            uint2 b[NT];
            #pragma unroll
            for (int t = 0; t < NT; t++)
                b[t] = *(const uint2*)&Wp[(((wn * NT + t) * KC8 + kc) * 32 + lane) * 2];
            #pragma unroll
            for (int mi = 0; mi < MI; mi++) {
                const float* ar = A0 + (wm * (TILE / 2) + mi * 16 + g) * KP + kc * 8 + tg;
                uint32_t a[4];
                a[0] = f2tf32(ar[0]);
                a[1] = f2tf32(ar[8 * KP]);
                a[2] = f2tf32(ar[4]);
                a[3] = f2tf32(ar[8 * KP + 4]);
                #pragma unroll
                for (int t = 0; t < NT; t++)
                    mma_tf32(acc[mi][t], a, (const uint32_t*)&b[t]);
            }
        }

        // u-add (+folded bias) + relu, record dsts, then release buf[par]
        const uint32_t* U0 = Ubuf + par * U_W32;
        int d0[MI], d1[MI];
        #pragma unroll
        for (int mi = 0; mi < MI; mi++) {
            int r0 = wm * (TILE / 2) + mi * 16 + g;
            d0[mi] = sdst[par * TILE + r0];
            d1[mi] = sdst[par * TILE + r0 + 8];
            #pragma unroll
            for (int t = 0; t < NT; t++) {
                int hw = wn * (F / 8) + t * 4 + tg;
                __half2 u0 = *(const __half2*)&U0[(size_t)r0 * UW + hw];
                __half2 u1 = *(const __half2*)&U0[(size_t)(r0 + 8) * UW + hw];
                acc[mi][t][0] = fmaxf(acc[mi][t][0] + __low2float(u0),  0.0f);
                acc[mi][t][1] = fmaxf(acc[mi][t][1] + __high2float(u0), 0.0f);
                acc[mi][t][2] = fmaxf(acc[mi][t][2] + __low2float(u1),  0.0f);
                acc[mi][t][3] = fmaxf(acc[mi][t][3] + __high2float(u1), 0.0f);
            }
        }
        __syncthreads();   // all reads of buf[par]/sdst[par] done

        // issue gather for tile+2*stride into buf[par]; overlaps atomics AND next tile's phases
        int t2 = tile + 2 * stride;
        if (t2 < nTiles) {
            gather(t2, par, ps, pd);
            CP_COMMIT();
            int t3 = t2 + stride;
            if (t3 < nTiles) { ps = src[t3 * TILE + row]; pd = dst[t3 * TILE + row]; }
        }

        // scalar atomic scatter with per-element zero-skip
        #pragma unroll
        for (int mi = 0; mi < MI; mi++) {
            float* row0 = agg + (size_t)d0[mi] * F;
            float* row1 = agg + (size_t)d1[mi] * F;
            #pragma unroll
            for (int t = 0; t < NT; t++) {
                int n = wn * (F / 4) + t * 8 + tg * 2;
                if (acc[mi][t][0] > 0.0f) atomicAdd(&row0[n], acc[mi][t][0]);
                if (acc[mi][t][1] > 0.0f) atomicAdd(&row0[n + 1], acc[mi][t][1]);
                if (acc[mi][t][2] > 0.0f) atomicAdd(&row1[n], acc[mi][t][2]);
                if (acc[mi][t][3] > 0.0f) atomicAdd(&row1[n + 1], acc[mi][t][3]);
            }
        }
        par ^= 1;
    }
}

// ---------------- elementwise node kernel (bs pre-folded into s) ----------------
template <int F, bool WRITE_FEAT>
__global__ __launch_bounds__(256) void nodeel_kernel(
    const float* __restrict__ agg, const __half2* __restrict__ s,
    const float* __restrict__ Wc, const float* __restrict__ bc,
    const int* __restrict__ gid, const float* __restrict__ deg, const float* __restrict__ gcnt,
    float* __restrict__ fout, float* __restrict__ score)
{
    const int gw = (blockIdx.x * 256 + threadIdx.x) >> 5;
    const int lane = threadIdx.x & 31;
    const int nw = (gridDim.x * 256) >> 5;
    const float bcv = __ldg(bc);

    for (int n = gw; n < NN; n += nw) {
        float inv = 1.0f / fmaxf(__ldg(&deg[n]), 1.0f);
        const float* arow = agg + (size_t)n * F;
        const __half2* srow = s + (size_t)n * (F / 2);
        float* frow = fout + (size_t)n * F;
        float cp = 0.0f;
        #pragma unroll
        for (int c = lane * 4; c < F; c += 128) {
            float4 a = *(const float4*)&arow[c];
            __half2 s0 = srow[c / 2];
            __half2 s1 = srow[c / 2 + 1];
            float v0 = fmaxf(a.x * inv + __low2float(s0),  0.0f);
            float v1 = fmaxf(a.y * inv + __high2float(s0), 0.0f);
            float v2 = fmaxf(a.z * inv + __low2float(s1),  0.0f);
            float v3 = fmaxf(a.w * inv + __high2float(s1), 0.0f);
            if (WRITE_FEAT) {
                float4 o; o.x = v0; o.y = v1; o.z = v2; o.w = v3;
                *(float4*)&frow[c] = o;
            }
            cp += v0 * __ldg(&Wc[c]) + v1 * __ldg(&Wc[c + 1])
                + v2 * __ldg(&Wc[c + 2]) + v3 * __ldg(&Wc[c + 3]);
        }
        #pragma unroll
        for (int off = 16; off; off >>= 1)
            cp += __shfl_xor_sync(0xFFFFFFFFu, cp, off);
        if (lane == 0) {
            int gg = gid[n];
            atomicAdd(&score[gg], (cp + bcv) / fmaxf(__ldg(&gcnt[gg]), 1.0f));
        }
    }
}

// ---------------- host side ----------------
template <typename Kern>
static int grid_for(Kern k, int smem_bytes, int tiles, int nsm, int block) {
    cudaFuncSetAttribute(k, cudaFuncAttributeMaxDynamicSharedMemorySize, smem_bytes);
    int occ = 1;
    cudaOccupancyMaxActiveBlocksPerMultiprocessor(&occ, k, block, smem_bytes);
    if (occ < 1) occ = 1;
    int g = nsm * occ;
    if (g > tiles) g = tiles;
    return g;
}

template <int FIN, int F, int FK, int TILE>
static void launch_us(const float* xin, const float* Wmx, const float* Ws,
                      const float* bm, const float* bs,
                      __half2* u, __half2* s, int col_off, int nsm)
{
    constexpr int KP = FIN + 4;
    const int smem = FIN * 2 * FK * 4 + TILE * KP * 4;
    int g = grid_for(us_kernel<FIN, F, FK, TILE>, smem, (NN + TILE - 1) / TILE, nsm, 256);
    us_kernel<FIN, F, FK, TILE><<<g, 256, smem>>>(xin, Wmx, Ws, bm, bs, u, s, col_off);
}

template <int F, int TILE>
static void launch_edge(const __half2* u, const float* efeat, const int* src, const int* dst,
                        const float* Wme, float* agg, int nsm)
{
    const int smem = EFD * F * 4 + 2 * TILE * (EFD + 4) * 4 + 2 * TILE * (F / 2 + 4) * 4
                   + 2 * TILE * 4;
    int g = grid_for(edge_mma_kernel<F, TILE>, smem, EE / TILE, nsm, 256);
    edge_mma_kernel<F, TILE><<<g, 256, smem>>>(u, efeat, src, dst, Wme, agg);
}

template <int F, bool WRITE_FEAT>
static void launch_nodeel(const float* agg, const __half2* s, const float* const* Wl,
                          const int* gid, const float* deg, const float* gcnt,
                          float* fout, float* score, int nsm)
{
    nodeel_kernel<F, WRITE_FEAT><<<nsm * 8, 256>>>(agg, s, Wl[4], Wl[5], gid, deg, gcnt,
                                                   fout, score);
}

extern "C" void kernel_launch(void* const* d_in, const int* in_sizes, int n_in,
                              void* d_out, int out_size)
{
    const float* x   = (const float*)d_in[0];
    const float* e   = (const float*)d_in[1];
    const int*   src = (const int*)d_in[2];
    const int*   dst = (const int*)d_in[3];
    const int*   gid = (const int*)d_in[4];
    const float* W[4][6];
    for (int l = 0; l < 4; l++)
        for (int j = 0; j < 6; j++)
            W[l][j] = (const float*)d_in[5 + l * 6 + j];
    float* score = (float*)d_out;

    float *bufA, *bufB, *agg, *deg, *gcnt;
    __half2 *uh, *sh;
    cudaGetSymbolAddress((void**)&bufA, g_bufA);
    cudaGetSymbolAddress((void**)&bufB, g_bufB);
    cudaGetSymbolAddress((void**)&agg, g_agg);
    cudaGetSymbolAddress((void**)&uh, g_uh);
    cudaGetSymbolAddress((void**)&sh, g_sh);
    cudaGetSymbolAddress((void**)&deg, g_deg);
    cudaGetSymbolAddress((void**)&gcnt, g_gcnt);

    int nsm = 148;
    cudaDeviceGetAttribute(&nsm, cudaDevAttrMultiProcessorCount, 0);

    cudaMemsetAsync(deg, 0, NN * sizeof(float));
    cudaMemsetAsync(gcnt, 0, GG * sizeof(float));
    cudaMemsetAsync(score, 0, GG * sizeof(float));
    count_kernel<<<(EE + 255) / 256, 256>>>(dst, gid, deg, gcnt);

    // layer 0: FIN=32, F=64
    cudaMemsetAsync(agg, 0, (size_t)NN * 64 * sizeof(float));
    launch_us<32, 64, 64, 128>(x, W[0][0], W[0][2], W[0][1], W[0][3], uh, sh, 0, nsm);
    launch_edge<64, 128>(uh, e, src, dst, W[0][0] + 32 * 64, agg, nsm);
    launch_nodeel<64, true>(agg, sh, W[0], gid, deg, gcnt, bufA, score, nsm);

    // layer 1: FIN=64, F=128
    cudaMemsetAsync(agg, 0, (size_t)NN * 128 * sizeof(float));
    launch_us<64, 128, 128, 128>(bufA, W[1][0], W[1][2], W[1][1], W[1][3], uh, sh, 0, nsm);
    launch_edge<128, 128>(uh, e, src, dst, W[1][0] + 64 * 128, agg, nsm);
    launch_nodeel<128, true>(agg, sh, W[1], gid, deg, gcnt, bufB, score, nsm);

    // layer 2: FIN=128, F=128
    cudaMemsetAsync(agg, 0, (size_t)NN * 128 * sizeof(float));
    launch_us<128, 128, 128, 64>(bufB, W[2][0], W[2][2], W[2][1], W[2][3], uh, sh, 0, nsm);
    launch_edge<128, 128>(uh, e, src, dst, W[2][0] + 128 * 128, agg, nsm);
    launch_nodeel<128, true>(agg, sh, W[2], gid, deg, gcnt, bufA, score, nsm);

    // layer 3: FIN=128, F=256 (two column halves for us); final feat never consumed -> skip store
    cudaMemsetAsync(agg, 0, (size_t)NN * 256 * sizeof(float));
    launch_us<128, 256, 128, 64>(bufA, W[3][0], W[3][2], W[3][1], W[3][3], uh, sh, 0, nsm);
    launch_us<128, 256, 128, 64>(bufA, W[3][0], W[3][2], W[3][1], W[3][3], uh, sh, 128, nsm);
    launch_edge<256, 64>(uh, e, src, dst, W[3][0] + 128 * 256, agg, nsm);
    launch_nodeel<256, false>(agg, sh, W[3], gid, deg, gcnt, bufB, score, nsm);
}

// round 17
// speedup vs baseline: 1.0235x; 1.0235x over previous
#include <cuda_runtime.h>
#include <cuda_fp16.h>
#include <cstdint>

#define NN 50000
#define EE 800000
#define GG 512
#define EFD 16

// ---------------- scratch (no allocations allowed) ----------------
__device__ float g_bufA[NN * 256];
__device__ float g_bufB[NN * 256];
__device__ float g_agg[NN * 256];
__device__ __half g_uh[NN * 256];
__device__ __half g_sh[NN * 256];
__device__ float g_deg[NN];
__device__ float g_gcnt[GG];

// ---------------- helpers ----------------
__device__ __forceinline__ uint32_t f2tf32(float x) {
    uint32_t r;
    asm("cvt.rna.tf32.f32 %0, %1;" : "=r"(r) : "f"(x));
    return r;
}
__device__ __forceinline__ uint32_t smem_u32(const void* p) {
    uint32_t a;
    asm("{ .reg .u64 t; cvta.to.shared.u64 t, %1; cvt.u32.u64 %0, t; }" : "=r"(a) : "l"(p));
    return a;
}
__device__ __forceinline__ void cp16(uint32_t saddr, const void* gaddr) {
    asm volatile("cp.async.ca.shared.global [%0], [%1], 16;" :: "r"(saddr), "l"(gaddr) : "memory");
}
#define CP_COMMIT() asm volatile("cp.async.commit_group;" ::: "memory")
#define CP_WAIT(n)  asm volatile("cp.async.wait_group %0;" :: "n"(n) : "memory")

// D += A(16x8,row) * B(8x8,col), tf32 inputs, f32 accum
__device__ __forceinline__ void mma_tf32(float* d, const uint32_t* a, const uint32_t* b) {
    asm volatile(
        "mma.sync.aligned.m16n8k8.row.col.f32.tf32.tf32.f32 "
        "{%0,%1,%2,%3}, {%4,%5,%6,%7}, {%8,%9}, {%0,%1,%2,%3};"
        : "+f"(d[0]), "+f"(d[1]), "+f"(d[2]), "+f"(d[3])
        : "r"(a[0]), "r"(a[1]), "r"(a[2]), "r"(a[3]), "r"(b[0]), "r"(b[1]));
}

__global__ void count_kernel(const int* __restrict__ dst, const int* __restrict__ gid,
                             float* __restrict__ deg, float* __restrict__ gcnt) {
    int i = blockIdx.x * blockDim.x + threadIdx.x;
    if (i < EE) atomicAdd(&deg[dst[i]], 1.0f);
    if (i < NN) atomicAdd(&gcnt[gid[i]], 1.0f);
}

// ---------------- fused dense kernel ----------------
// u[:,co:+FK] = x@Wmx[:,co:+FK] + bm;  s[:,co:+FK] = x@Ws[:,co:+FK] + bs  (fp16 out)
template <int FIN, int F, int FK, int TILE>
__global__ __launch_bounds__(256)
void us_kernel(const float* __restrict__ xin,
               const float* __restrict__ Wmx, const float* __restrict__ Ws,
               const float* __restrict__ bm, const float* __restrict__ bs,
               __half2* __restrict__ uout, __half2* __restrict__ sout, int col_off)
{
    constexpr int KP = FIN + 4;
    constexpr int KC8 = FIN / 8;
    constexpr int N2 = 2 * FK;
    constexpr int NT = FK / 8;
    constexpr int MI = TILE / 64;
    constexpr int TPR = 256 / TILE;
    constexpr int W_U32 = FIN * N2;

    extern __shared__ char smem[];
    uint32_t* Wp = (uint32_t*)smem;
    float* Abuf = (float*)(smem + (size_t)W_U32 * 4);

    const int tid = threadIdx.x;
    const int w = tid >> 5, lane = tid & 31;
    const int wm = w >> 1, wn = w & 1;
    const int g = lane >> 2, tg = lane & 3;
    const int row = tid / TPR, h = tid % TPR;
    const uint32_t sbA = smem_u32(Abuf);

    for (int i = tid; i < FIN * N2; i += 256) {
        int k = i / N2, n = i % N2;
        float wv = (n < FK) ? Wmx[k * F + col_off + n] : Ws[k * F + col_off + (n - FK)];
        uint32_t val = f2tf32(wv);
        int T = n >> 3, kc = k >> 3;
        Wp[((T * KC8 + kc) * 32 + (n & 7) * 4 + (k & 3)) * 2 + ((k >> 2) & 1)] = val;
    }

    const int nTiles = (NN + TILE - 1) / TILE;
    const int stride = gridDim.x;

    auto gather = [&](int tile) {
        int grow = tile * TILE + row;
        if (grow >= NN) grow = NN - 1;
        uint32_t arow = sbA + (uint32_t)(row * KP) * 4;
        const char* xr = (const char*)(xin + (size_t)grow * FIN);
        #pragma unroll
        for (int c = h; c < FIN / 4; c += TPR) cp16(arow + c * 16, xr + c * 16);
    };

    int t0 = blockIdx.x;
    gather(t0);
    CP_COMMIT();

    __half2* outp = wn ? sout : uout;
    const float* bias = wn ? bs : bm;

    for (int tile = t0; tile < nTiles; tile += stride) {
        CP_WAIT(0);
        __syncthreads();

        float acc[MI][NT][4];
        #pragma unroll
        for (int mi = 0; mi < MI; mi++)
            #pragma unroll
            for (int t = 0; t < NT; t++)
                #pragma unroll
                for (int j = 0; j < 4; j++) acc[mi][t][j] = 0.0f;

        for (int kc = 0; kc < KC8; kc++) {
            uint2 b[NT];
            #pragma unroll
            for (int t = 0; t < NT; t++)
                b[t] = *(const uint2*)&Wp[(((wn * NT + t) * KC8 + kc) * 32 + lane) * 2];
            #pragma unroll
            for (int mi = 0; mi < MI; mi++) {
                const float* ar = Abuf + (wm * (TILE / 4) + mi * 16 + g) * KP + kc * 8 + tg;
                uint32_t a[4];
                a[0] = f2tf32(ar[0]);
                a[1] = f2tf32(ar[8 * KP]);
                a[2] = f2tf32(ar[4]);
                a[3] = f2tf32(ar[8 * KP + 4]);
                #pragma unroll
                for (int t = 0; t < NT; t++)
                    mma_tf32(acc[mi][t], a, (const uint32_t*)&b[t]);
            }
        }
        __syncthreads();

        int nxt = tile + stride;
        if (nxt < nTiles) { gather(nxt); CP_COMMIT(); }

        const int base = tile * TILE;
        #pragma unroll
        for (int mi = 0; mi < MI; mi++) {
            int r0 = wm * (TILE / 4) + mi * 16 + g;
            int gr0 = base + r0, gr1 = gr0 + 8;
            #pragma unroll
            for (int t = 0; t < NT; t++) {
                int n = t * 8 + tg * 2;
                float b0 = __ldg(&bias[col_off + n]);
                float b1 = __ldg(&bias[col_off + n + 1]);
                if (gr0 < NN)
                    outp[(size_t)gr0 * (F / 2) + (col_off + n) / 2] =
                        __floats2half2_rn(acc[mi][t][0] + b0, acc[mi][t][1] + b1);
                if (gr1 < NN)
                    outp[(size_t)gr1 * (F / 2) + (col_off + n) / 2] =
                        __floats2half2_rn(acc[mi][t][2] + b0, acc[mi][t][3] + b1);
            }
        }
    }
}

// ---------------- edge kernel: agg[dst] += relu(u[src] + e @ Wme), bias pre-folded into u ----------------
// Double-buffered A/U, 2-deep cp.async pipeline; MINB blocks/SM for latency hiding.
template <int F, int TILE, int MINB>
__global__ __launch_bounds__(256, MINB)
void edge_mma_kernel(const __half2* __restrict__ u, const float* __restrict__ efeat,
                     const int* __restrict__ src, const int* __restrict__ dst,
                     const float* __restrict__ Wme,
                     float* __restrict__ agg)
{
    constexpr int K = EFD;
    constexpr int KP = K + 4;
    constexpr int KC8 = 2;
    constexpr int NT = F / 32;
    constexpr int MI = TILE / 32;
    constexpr int TPR = 256 / TILE;
    constexpr int UW = F / 2 + 4;
    constexpr int W_U32 = K * F;
    constexpr int A_F32 = TILE * KP;
    constexpr int U_W32 = TILE * UW;

    extern __shared__ char smem[];
    uint32_t* Wp = (uint32_t*)smem;
    float* Abuf = (float*)(smem + (size_t)W_U32 * 4);                 // 2 * A_F32
    uint32_t* Ubuf = (uint32_t*)(Abuf + 2 * A_F32);                   // 2 * U_W32
    int* sdst = (int*)(Ubuf + 2 * U_W32);                             // 2 * TILE

    const int tid = threadIdx.x;
    const int w = tid >> 5, lane = tid & 31;
    const int wm = w >> 2, wn = w & 3;
    const int g = lane >> 2, tg = lane & 3;
    const int row = tid / TPR, h = tid % TPR;
    const uint32_t sbA = smem_u32(Abuf);
    const uint32_t sbU = smem_u32(Ubuf);

    for (int i = tid; i < K * F; i += 256) {
        int k = i / F, n = i % F;
        uint32_t val = f2tf32(Wme[k * F + n]);
        int T = n >> 3, kc = k >> 3;
        Wp[((T * KC8 + kc) * 32 + (n & 7) * 4 + (k & 3)) * 2 + ((k >> 2) & 1)] = val;
    }

    const int nTiles = EE / TILE;
    const int stride = gridDim.x;

    auto gather = [&](int tile, int par, int srow, int sd) {
        int base = tile * TILE;
        if (h == 0) sdst[par * TILE + row] = sd;
        uint32_t arow = sbA + (uint32_t)(par * A_F32 + row * KP) * 4;
        const char* er = (const char*)(efeat + (size_t)(base + row) * EFD);
        #pragma unroll
        for (int c = h; c < EFD / 4; c += TPR) cp16(arow + c * 16, er + c * 16);
        uint32_t urow = sbU + (uint32_t)(par * U_W32 + row * UW) * 4;
        const char* ur = (const char*)(u + (size_t)srow * (F / 2));
        #pragma unroll
        for (int c = h; c < F / 8; c += TPR) cp16(urow + c * 16, ur + c * 16);
    };

    int t0 = blockIdx.x;
    int ps = src[t0 * TILE + row];
    int pd = dst[t0 * TILE + row];
    gather(t0, 0, ps, pd);
    CP_COMMIT();
    int t1 = t0 + stride;
    if (t1 < nTiles) {
        ps = src[t1 * TILE + row];
        pd = dst[t1 * TILE + row];
        gather(t1, 1, ps, pd);
        CP_COMMIT();
        int tn = t0 + 2 * stride;
        if (tn < nTiles) { ps = src[tn * TILE + row]; pd = dst[tn * TILE + row]; }
    }

    int par = 0;
    for (int tile = t0; tile < nTiles; tile += stride) {
        if (tile + stride < nTiles) CP_WAIT(1); else CP_WAIT(0);
        __syncthreads();

        float acc[MI][NT][4];
        #pragma unroll
        for (int mi = 0; mi < MI; mi++)
            #pragma unroll
            for (int t = 0; t < NT; t++)
                #pragma unroll
                for (int j = 0; j < 4; j++) acc[mi][t][j] = 0.0f;

        const float* A0 = Abuf + par * A_F32;
        #pragma unroll
        for (int kc = 0; kc < KC8; kc++) {
            uint2 b[NT];
            #pragma unroll
            for (int t = 0; t < NT; t++)
                b[t] = *(const uint2*)&Wp[(((wn * NT + t) * KC8 + kc) * 32 + lane) * 2];
            #pragma unroll
            for (int mi = 0; mi < MI; mi++) {
                const float* ar = A0 + (wm * (TILE / 2) + mi * 16 + g) * KP + kc * 8 + tg;
                uint32_t a[4];
                a[0] = f2tf32(ar[0]);
                a[1] = f2tf32(ar[8 * KP]);
                a[2] = f2tf32(ar[4]);
                a[3] = f2tf32(ar[8 * KP + 4]);
                #pragma unroll
                for (int t = 0; t < NT; t++)
                    mma_tf32(acc[mi][t], a, (const uint32_t*)&b[t]);
            }
        }

        const uint32_t* U0 = Ubuf + par * U_W32;
        int d0[MI], d1[MI];
        #pragma unroll
        for (int mi = 0; mi < MI; mi++) {
            int r0 = wm * (TILE / 2) + mi * 16 + g;
            d0[mi] = sdst[par * TILE + r0];
            d1[mi] = sdst[par * TILE + r0 + 8];
            #pragma unroll
            for (int t = 0; t < NT; t++) {
                int hw = wn * (F / 8) + t * 4 + tg;
                __half2 u0 = *(const __half2*)&U0[(size_t)r0 * UW + hw];
                __half2 u1 = *(const __half2*)&U0[(size_t)(r0 + 8) * UW + hw];
                acc[mi][t][0] = fmaxf(acc[mi][t][0] + __low2float(u0),  0.0f);
                acc[mi][t][1] = fmaxf(acc[mi][t][1] + __high2float(u0), 0.0f);
                acc[mi][t][2] = fmaxf(acc[mi][t][2] + __low2float(u1),  0.0f);
                acc[mi][t][3] = fmaxf(acc[mi][t][3] + __high2float(u1), 0.0f);
            }
        }
        __syncthreads();

        int t2 = tile + 2 * stride;
        if (t2 < nTiles) {
            gather(t2, par, ps, pd);
            CP_COMMIT();
            int t3 = t2 + stride;
            if (t3 < nTiles) { ps = src[t3 * TILE + row]; pd = dst[t3 * TILE + row]; }
        }

        #pragma unroll
        for (int mi = 0; mi < MI; mi++) {
            float* row0 = agg + (size_t)d0[mi] * F;
            float* row1 = agg + (size_t)d1[mi] * F;
            #pragma unroll
            for (int t = 0; t < NT; t++) {
                int n = wn * (F / 4) + t * 8 + tg * 2;
                if (acc[mi][t][0] > 0.0f) atomicAdd(&row0[n], acc[mi][t][0]);
                if (acc[mi][t][1] > 0.0f) atomicAdd(&row0[n + 1], acc[mi][t][1]);
                if (acc[mi][t][2] > 0.0f) atomicAdd(&row1[n], acc[mi][t][2]);
                if (acc[mi][t][3] > 0.0f) atomicAdd(&row1[n + 1], acc[mi][t][3]);
            }
        }
        par ^= 1;
    }
}

// ---------------- elementwise node kernel (bs pre-folded into s) ----------------
template <int F, bool WRITE_FEAT>
__global__ __launch_bounds__(256) void nodeel_kernel(
    const float* __restrict__ agg, const __half2* __restrict__ s,
    const float* __restrict__ Wc, const float* __restrict__ bc,
    const int* __restrict__ gid, const float* __restrict__ deg, const float* __restrict__ gcnt,
    float* __restrict__ fout, float* __restrict__ score)
{
    const int gw = (blockIdx.x * 256 + threadIdx.x) >> 5;
    const int lane = threadIdx.x & 31;
    const int nw = (gridDim.x * 256) >> 5;
    const float bcv = __ldg(bc);

    for (int n = gw; n < NN; n += nw) {
        float inv = 1.0f / fmaxf(__ldg(&deg[n]), 1.0f);
        const float* arow = agg + (size_t)n * F;
        const __half2* srow = s + (size_t)n * (F / 2);
        float* frow = fout + (size_t)n * F;
        float cp = 0.0f;
        #pragma unroll
        for (int c = lane * 4; c < F; c += 128) {
            float4 a = *(const float4*)&arow[c];
            __half2 s0 = srow[c / 2];
            __half2 s1 = srow[c / 2 + 1];
            float v0 = fmaxf(a.x * inv + __low2float(s0),  0.0f);
            float v1 = fmaxf(a.y * inv + __high2float(s0), 0.0f);
            float v2 = fmaxf(a.z * inv + __low2float(s1),  0.0f);
            float v3 = fmaxf(a.w * inv + __high2float(s1), 0.0f);
            if (WRITE_FEAT) {
                float4 o; o.x = v0; o.y = v1; o.z = v2; o.w = v3;
                *(float4*)&frow[c] = o;
            }
            cp += v0 * __ldg(&Wc[c]) + v1 * __ldg(&Wc[c + 1])
                + v2 * __ldg(&Wc[c + 2]) + v3 * __ldg(&Wc[c + 3]);
        }
        #pragma unroll
        for (int off = 16; off; off >>= 1)
            cp += __shfl_xor_sync(0xFFFFFFFFu, cp, off);
        if (lane == 0) {
            int gg = gid[n];
            atomicAdd(&score[gg], (cp + bcv) / fmaxf(__ldg(&gcnt[gg]), 1.0f));
        }
    }
}

// ---------------- host side ----------------
template <typename Kern>
static int grid_for(Kern k, int smem_bytes, int tiles, int nsm, int block) {
    cudaFuncSetAttribute(k, cudaFuncAttributeMaxDynamicSharedMemorySize, smem_bytes);
    int occ = 1;
    cudaOccupancyMaxActiveBlocksPerMultiprocessor(&occ, k, block, smem_bytes);
    if (occ < 1) occ = 1;
    int g = nsm * occ;
    if (g > tiles) g = tiles;
    return g;
}

template <int FIN, int F, int FK, int TILE>
static void launch_us(const float* xin, const float* Wmx, const float* Ws,
                      const float* bm, const float* bs,
                      __half2* u, __half2* s, int col_off, int nsm)
{
    constexpr int KP = FIN + 4;
    const int smem = FIN * 2 * FK * 4 + TILE * KP * 4;
    int g = grid_for(us_kernel<FIN, F, FK, TILE>, smem, (NN + TILE - 1) / TILE, nsm, 256);
    us_kernel<FIN, F, FK, TILE><<<g, 256, smem>>>(xin, Wmx, Ws, bm, bs, u, s, col_off);
}

template <int F, int TILE, int MINB>
static void launch_edge(const __half2* u, const float* efeat, const int* src, const int* dst,
                        const float* Wme, float* agg, int nsm)
{
    const int smem = EFD * F * 4 + 2 * TILE * (EFD + 4) * 4 + 2 * TILE * (F / 2 + 4) * 4
                   + 2 * TILE * 4;
    int g = grid_for(edge_mma_kernel<F, TILE, MINB>, smem, EE / TILE, nsm, 256);
    edge_mma_kernel<F, TILE, MINB><<<g, 256, smem>>>(u, efeat, src, dst, Wme, agg);
}

template <int F, bool WRITE_FEAT>
static void launch_nodeel(const float* agg, const __half2* s, const float* const* Wl,
                          const int* gid, const float* deg, const float* gcnt,
                          float* fout, float* score, int nsm)
{
    nodeel_kernel<F, WRITE_FEAT><<<nsm * 8, 256>>>(agg, s, Wl[4], Wl[5], gid, deg, gcnt,
                                                   fout, score);
}

extern "C" void kernel_launch(void* const* d_in, const int* in_sizes, int n_in,
                              void* d_out, int out_size)
{
    const float* x   = (const float*)d_in[0];
    const float* e   = (const float*)d_in[1];
    const int*   src = (const int*)d_in[2];
    const int*   dst = (const int*)d_in[3];
    const int*   gid = (const int*)d_in[4];
    const float* W[4][6];
    for (int l = 0; l < 4; l++)
        for (int j = 0; j < 6; j++)
            W[l][j] = (const float*)d_in[5 + l * 6 + j];
    float* score = (float*)d_out;

    float *bufA, *bufB, *agg, *deg, *gcnt;
    __half2 *uh, *sh;
    cudaGetSymbolAddress((void**)&bufA, g_bufA);
    cudaGetSymbolAddress((void**)&bufB, g_bufB);
    cudaGetSymbolAddress((void**)&agg, g_agg);
    cudaGetSymbolAddress((void**)&uh, g_uh);
    cudaGetSymbolAddress((void**)&sh, g_sh);
    cudaGetSymbolAddress((void**)&deg, g_deg);
    cudaGetSymbolAddress((void**)&gcnt, g_gcnt);

    int nsm = 148;
    cudaDeviceGetAttribute(&nsm, cudaDevAttrMultiProcessorCount, 0);

    cudaMemsetAsync(deg, 0, NN * sizeof(float));
    cudaMemsetAsync(gcnt, 0, GG * sizeof(float));
    cudaMemsetAsync(score, 0, GG * sizeof(float));
    count_kernel<<<(EE + 255) / 256, 256>>>(dst, gid, deg, gcnt);

    // layer 0: FIN=32, F=64
    cudaMemsetAsync(agg, 0, (size_t)NN * 64 * sizeof(float));
    launch_us<32, 64, 64, 128>(x, W[0][0], W[0][2], W[0][1], W[0][3], uh, sh, 0, nsm);
    launch_edge<64, 128, 3>(uh, e, src, dst, W[0][0] + 32 * 64, agg, nsm);
    launch_nodeel<64, true>(agg, sh, W[0], gid, deg, gcnt, bufA, score, nsm);

    // layer 1: FIN=64, F=128 (TILE=64, 3 blocks/SM)
    cudaMemsetAsync(agg, 0, (size_t)NN * 128 * sizeof(float));
    launch_us<64, 128, 128, 128>(bufA, W[1][0], W[1][2], W[1][1], W[1][3], uh, sh, 0, nsm);
    launch_edge<128, 64, 3>(uh, e, src, dst, W[1][0] + 64 * 128, agg, nsm);
    launch_nodeel<128, true>(agg, sh, W[1], gid, deg, gcnt, bufB, score, nsm);

    // layer 2: FIN=128, F=128 (TILE=64, 3 blocks/SM)
    cudaMemsetAsync(agg, 0, (size_t)NN * 128 * sizeof(float));
    launch_us<128, 128, 128, 64>(bufB, W[2][0], W[2][2], W[2][1], W[2][3], uh, sh, 0, nsm);
    launch_edge<128, 64, 3>(uh, e, src, dst, W[2][0] + 128 * 128, agg, nsm);
    launch_nodeel<128, true>(agg, sh, W[2], gid, deg, gcnt, bufA, score, nsm);

    // layer 3: FIN=128, F=256 (two column halves for us); final feat never consumed -> skip store
    cudaMemsetAsync(agg, 0, (size_t)NN * 256 * sizeof(float));
    launch_us<128, 256, 128, 64>(bufA, W[3][0], W[3][2], W[3][1], W[3][3], uh, sh, 0, nsm);
    launch_us<128, 256, 128, 64>(bufA, W[3][0], W[3][2], W[3][1], W[3][3], uh, sh, 128, nsm);
    launch_edge<256, 64, 2>(uh, e, src, dst, W[3][0] + 128 * 256, agg, nsm);
    launch_nodeel<256, false>(agg, sh, W[3], gid, deg, gcnt, bufB, score, nsm);
}